// round 6
// baseline (speedup 1.0000x reference)
#include <cuda_runtime.h>
#include <cstdint>

// Problem constants
#define ORDER  3
#define POINTS 16
#define NN     2048
#define D1     64
#define D2     32
#define POOL1  32
#define POOL2  8
#define LABELS 10
#define OP     (ORDER*POINTS)   // 48
#define PBLK   64               // pooling blocks
#define PROWS  (NN/PBLK)        // 32 rows per pooling block

// Scratch (no allocation allowed -> __device__ globals)
__device__ float g_ms[NN * OP];          // [2048, 48]
__device__ float g_h2[NN * D2];          // [2048, 32]
__device__ float g_e[NN * POOL2];        // [2048, 8]  exp(scores), unnormalized
__device__ float g_part[PBLK * POOL2 * D2]; // per-block pooled partials [64][256]

// ---------------------------------------------------------------------------
// Packed f32x2 helpers (sm_103a; PTX-only path, ptxas never emits from C++)
// ---------------------------------------------------------------------------
__device__ __forceinline__ unsigned long long f2_pack(float lo, float hi) {
    unsigned long long d;
    asm("mov.b64 %0, {%1, %2};" : "=l"(d) : "f"(lo), "f"(hi));
    return d;
}
__device__ __forceinline__ void f2_unpack(unsigned long long v, float& lo, float& hi) {
    asm("mov.b64 {%0, %1}, %2;" : "=f"(lo), "=f"(hi) : "l"(v));
}
__device__ __forceinline__ unsigned long long f2_mul(unsigned long long a, unsigned long long b) {
    unsigned long long d;
    asm("mul.rn.f32x2 %0, %1, %2;" : "=l"(d) : "l"(a), "l"(b));
    return d;
}
__device__ __forceinline__ unsigned long long f2_add(unsigned long long a, unsigned long long b) {
    unsigned long long d;
    asm("add.rn.f32x2 %0, %1, %2;" : "=l"(d) : "l"(a), "l"(b));
    return d;
}
__device__ __forceinline__ unsigned long long f2_fma(unsigned long long a, unsigned long long b,
                                                     unsigned long long c) {
    unsigned long long d;
    asm("fma.rn.f32x2 %0, %1, %2, %3;" : "=l"(d) : "l"(a), "l"(b), "l"(c));
    return d;
}

// Packed Cody-Waite reduce of 2 values, then 2 MUFU cos, accumulate packed.
// 6 packed fma-pipe ops per 2 cos (~6 rt/cos) + 2 MUFU (8 rt/cos, binding).
__device__ __forceinline__ unsigned long long f2_cos_acc(
    unsigned long long w, unsigned long long a,
    unsigned long long inv2pi2, unsigned long long magic2,
    unsigned long long nmagic2, unsigned long long nhi2,
    unsigned long long nlo2, unsigned long long acc) {
    unsigned long long x2 = f2_mul(w, a);
    unsigned long long kb = f2_fma(x2, inv2pi2, magic2);  // round-to-nearest
    unsigned long long k2 = f2_add(kb, nmagic2);
    unsigned long long r2 = f2_fma(k2, nhi2, x2);
    r2 = f2_fma(k2, nlo2, r2);
    float rl, rh;
    f2_unpack(r2, rl, rh);
    return f2_add(acc, f2_pack(__cosf(rl), __cosf(rh)));
}

// ---------------------------------------------------------------------------
// Kernel 1: feats[o,p,i] = mean_j cos(wm[o,p] * adj[o,i,j])
// One block per (o,i) row; 256 threads; dual float4 loads hoisted for ILP.
// MUFU floor: 201M cos / 2368 cos-per-cyc chip ~= 85K cyc (~45us @NAT).
// Magic rounding exact: |x/2pi| <= ~160 << 2^22.
// ---------------------------------------------------------------------------
__global__ __launch_bounds__(256, 2) void k_feats(const float* __restrict__ adj,
                                                  const float* __restrict__ wm) {
    const int bo = blockIdx.x;        // 0..6143
    const int o  = bo >> 11;
    const int i  = bo & (NN - 1);
    const int tid  = threadIdx.x;
    const int lane = tid & 31;
    const int wrp  = tid >> 5;

    const float INV2PI   = 0.15915494309189535f;
    const float TWOPI_HI = 6.28125f;               // exact in fp32 (9 mantissa bits)
    const float TWOPI_LO = 1.9353071795864769e-3f; // 2pi - hi
    const float MAGIC    = 12582912.0f;            // 1.5 * 2^23
    const unsigned long long inv2pi2  = f2_pack(INV2PI, INV2PI);
    const unsigned long long magic2   = f2_pack(MAGIC, MAGIC);
    const unsigned long long nmagic2  = f2_pack(-MAGIC, -MAGIC);
    const unsigned long long nhi2     = f2_pack(-TWOPI_HI, -TWOPI_HI);
    const unsigned long long nlo2     = f2_pack(-TWOPI_LO, -TWOPI_LO);

    unsigned long long w2[POINTS];
#pragma unroll
    for (int p = 0; p < POINTS; p++) {
        float w = wm[o * POINTS + p];
        w2[p] = f2_pack(w, w);
    }

    const float4* row4 =
        (const float4*)(adj + (size_t)o * NN * NN + (size_t)i * NN);

    // hoist both loads: in flight before the compute chain starts
    float4 a0 = row4[tid];
    float4 a1 = row4[256 + tid];
    unsigned long long d0 = f2_pack(a0.x, a0.y);
    unsigned long long d1 = f2_pack(a0.z, a0.w);
    unsigned long long d2 = f2_pack(a1.x, a1.y);
    unsigned long long d3 = f2_pack(a1.z, a1.w);

    unsigned long long acc2[POINTS];
    const unsigned long long zero2 = f2_pack(0.0f, 0.0f);
#pragma unroll
    for (int p = 0; p < POINTS; p++) acc2[p] = zero2;

#pragma unroll
    for (int p = 0; p < POINTS; p++) {
        unsigned long long a = acc2[p];
        a = f2_cos_acc(w2[p], d0, inv2pi2, magic2, nmagic2, nhi2, nlo2, a);
        a = f2_cos_acc(w2[p], d1, inv2pi2, magic2, nmagic2, nhi2, nlo2, a);
        a = f2_cos_acc(w2[p], d2, inv2pi2, magic2, nmagic2, nhi2, nlo2, a);
        a = f2_cos_acc(w2[p], d3, inv2pi2, magic2, nmagic2, nhi2, nlo2, a);
        acc2[p] = a;
    }

    // collapse packed lanes, then warp reduce
    float acc[POINTS];
#pragma unroll
    for (int p = 0; p < POINTS; p++) {
        float lo, hi;
        f2_unpack(acc2[p], lo, hi);
        acc[p] = lo + hi;
    }
#pragma unroll
    for (int p = 0; p < POINTS; p++) {
#pragma unroll
        for (int off = 16; off > 0; off >>= 1)
            acc[p] += __shfl_xor_sync(0xFFFFFFFFu, acc[p], off);
    }

    __shared__ float red[8][POINTS];
    if (lane == 0) {
#pragma unroll
        for (int p = 0; p < POINTS; p++) red[wrp][p] = acc[p];
    }
    __syncthreads();

    if (tid < POINTS) {
        float s = 0.0f;
#pragma unroll
        for (int w = 0; w < 8; w++) s += red[w][tid];
        g_ms[i * OP + o * POINTS + tid] = s * (1.0f / (float)NN);
    }
}

// ---------------------------------------------------------------------------
// Kernel 2 (fused MLP): 4 rows per 256-thread block (row = tid>>6):
//   h1 = relu(ms@w1+b1); h2 = relu(h1@w2+b2);
//   abstract = tanh(h2@p1+pb1); e = exp(abstract@p2+pb2)
// Raw exp (no max-shift) is exact softmax algebraically; scores are bounded
// (tanh-activations times 0.1-scale weights -> |s| <~ 3).
// ---------------------------------------------------------------------------
__global__ __launch_bounds__(256) void k_mlp(const float* __restrict__ w1,
                                             const float* __restrict__ b1,
                                             const float* __restrict__ w2,
                                             const float* __restrict__ b2,
                                             const float* __restrict__ p1,
                                             const float* __restrict__ pb1,
                                             const float* __restrict__ p2,
                                             const float* __restrict__ pb2) {
    const int tid = threadIdx.x;
    const int r   = tid >> 6;               // 0..3 row-in-block
    const int t   = tid & 63;               // 0..63 lane-in-row
    const int i   = blockIdx.x * 4 + r;     // global row

    __shared__ float sms[4][OP];
    __shared__ float sh1[4][D1];
    __shared__ float sh2[4][D2];
    __shared__ float sab[4][POOL1];

    if (t < OP) sms[r][t] = g_ms[i * OP + t];
    __syncthreads();

    // h1 (64 threads per row, one output each)
    {
        float s = b1[t];
#pragma unroll
        for (int k = 0; k < OP; k++) s = fmaf(sms[r][k], w1[k * D1 + t], s);
        sh1[r][t] = fmaxf(s, 0.0f);
    }
    __syncthreads();

    // h2 (32 threads per row)
    if (t < D2) {
        float s = b2[t];
#pragma unroll
        for (int k = 0; k < D1; k++) s = fmaf(sh1[r][k], w2[k * D2 + t], s);
        float h = fmaxf(s, 0.0f);
        sh2[r][t] = h;
        g_h2[i * D2 + t] = h;
    }
    __syncthreads();

    // abstract (32 threads per row)
    if (t < POOL1) {
        float a = pb1[t];
#pragma unroll
        for (int k = 0; k < D2; k++) a = fmaf(sh2[r][k], p1[k * POOL1 + t], a);
        sab[r][t] = tanhf(a);
    }
    __syncthreads();

    // e = exp(scores) (8 threads per row)
    if (t < POOL2) {
        float s = pb2[t];
#pragma unroll
        for (int k = 0; k < POOL1; k++) s = fmaf(sab[r][k], p2[k * POOL2 + t], s);
        g_e[i * POOL2 + t] = expf(s);
    }
}

// ---------------------------------------------------------------------------
// Kernel 3: pooled partials. 64 blocks x 256 threads; block b covers rows
// [b*32, b*32+32). Each warp handles 4 rows: one coalesced LDG of the h2 row
// (lane = d), one 8-float e load broadcast via shfl, 8 FFMA per row.
// Deterministic per-block partials (no atomics -> replay-deterministic).
// ---------------------------------------------------------------------------
__global__ __launch_bounds__(256) void k_pool() {
    const int b    = blockIdx.x;
    const int tid  = threadIdx.x;
    const int lane = tid & 31;
    const int wrp  = tid >> 5;       // 0..7

    float acc[POOL2];
#pragma unroll
    for (int k = 0; k < POOL2; k++) acc[k] = 0.0f;

    const int i0 = b * PROWS + wrp * 4;
#pragma unroll
    for (int t = 0; t < 4; t++) {
        int i = i0 + t;
        float h2v = g_h2[i * D2 + lane];
        float ev  = (lane < POOL2) ? g_e[i * POOL2 + lane] : 0.0f;
#pragma unroll
        for (int k = 0; k < POOL2; k++) {
            float ek = __shfl_sync(0xFFFFFFFFu, ev, k);
            acc[k] = fmaf(ek, h2v, acc[k]);
        }
    }

    __shared__ float part[8][POOL2 * D2];   // 8 warps x 256
#pragma unroll
    for (int k = 0; k < POOL2; k++) part[wrp][k * D2 + lane] = acc[k];
    __syncthreads();

    // 256 threads: sum the 8 warp partials -> block partial
    float s = 0.0f;
#pragma unroll
    for (int w = 0; w < 8; w++) s += part[w][tid];
    g_part[b * (POOL2 * D2) + tid] = s;
}

// ---------------------------------------------------------------------------
// Kernel 4 (single block, 256 threads): e-column sums, normalize pooled g,
// classifier logits, log_softmax -> out[10].
// ---------------------------------------------------------------------------
__global__ __launch_bounds__(256) void k_final(const float* __restrict__ cw,
                                               const float* __restrict__ cb,
                                               float* __restrict__ out) {
    const int tid = threadIdx.x;

    __shared__ float sred[32][POOL2];
    __shared__ float ssum[POOL2];
    __shared__ float sg[POOL2 * D2];
    __shared__ float slog[LABELS];
    __shared__ float snorm[2];

    // ---- ssum[k] = sum_i e[i][k]; thread j: k = j&7, group j>>3 covers 64 rows
    {
        int k   = tid & 7;
        int grp = tid >> 3;            // 0..31
        float s = 0.0f;
        int r0 = grp * 64;
        for (int r = r0; r < r0 + 64; r++) s += g_e[r * POOL2 + k];
        sred[grp][k] = s;
    }
    __syncthreads();
    if (tid < POOL2) {
        float s = 0.0f;
#pragma unroll
        for (int g = 0; g < 32; g++) s += sred[g][tid];
        ssum[tid] = s;
    }
    __syncthreads();

    // ---- sg[j] = (sum_b g_part[b][j]) / ssum[j>>5]
    {
        float s = 0.0f;
        for (int b = 0; b < PBLK; b++) s += g_part[b * (POOL2 * D2) + tid];
        sg[tid] = s / ssum[tid >> 5];
    }
    __syncthreads();

    // ---- logits = g @ cw + cb
    if (tid < LABELS) {
        float s = cb[tid];
#pragma unroll
        for (int j = 0; j < POOL2 * D2; j++)
            s = fmaf(sg[j], cw[j * LABELS + tid], s);
        slog[tid] = s;
    }
    __syncthreads();

    // ---- log_softmax
    if (tid == 0) {
        float m = -1e30f;
#pragma unroll
        for (int l = 0; l < LABELS; l++) m = fmaxf(m, slog[l]);
        float s = 0.0f;
#pragma unroll
        for (int l = 0; l < LABELS; l++) s += expf(slog[l] - m);
        snorm[0] = m;
        snorm[1] = logf(s);
    }
    __syncthreads();
    if (tid < LABELS) {
        out[tid] = slog[tid] - snorm[0] - snorm[1];
    }
}

// ---------------------------------------------------------------------------
extern "C" void kernel_launch(void* const* d_in, const int* in_sizes, int n_in,
                              void* d_out, int out_size) {
    const float* adj = (const float*)d_in[0];
    const float* wm  = (const float*)d_in[1];
    const float* w1  = (const float*)d_in[2];
    const float* b1  = (const float*)d_in[3];
    const float* w2  = (const float*)d_in[4];
    const float* b2  = (const float*)d_in[5];
    const float* p1  = (const float*)d_in[6];
    const float* pb1 = (const float*)d_in[7];
    const float* p2  = (const float*)d_in[8];
    const float* pb2 = (const float*)d_in[9];
    const float* cw  = (const float*)d_in[10];
    const float* cb  = (const float*)d_in[11];
    float* out = (float*)d_out;

    k_feats<<<ORDER * NN, 256>>>(adj, wm);
    k_mlp<<<NN / 4, 256>>>(w1, b1, w2, b2, p1, pb1, p2, pb2);
    k_pool<<<PBLK, 256>>>();
    k_final<<<1, 256>>>(cw, cb, out);
}

// round 10
// speedup vs baseline: 1.1676x; 1.1676x over previous
#include <cuda_runtime.h>
#include <cstdint>

// Problem constants
#define ORDER  3
#define POINTS 16
#define NN     2048
#define D1     64
#define D2     32
#define POOL1  32
#define POOL2  8
#define LABELS 10
#define OP     (ORDER*POINTS)   // 48
#define PBLK   64               // pooling blocks
#define PROWS  (NN/PBLK)        // 32 rows per pooling block

// Scratch (no allocation allowed -> __device__ globals)
__device__ float g_ms[NN * OP];          // [2048, 48]
__device__ float g_h2[NN * D2];          // [2048, 32]
__device__ float g_e[NN * POOL2];        // [2048, 8]  exp(scores), unnormalized
__device__ float g_part[PBLK * POOL2 * D2]; // per-block pooled partials [64][256]
__device__ float g_esum[PBLK * POOL2];      // per-block e-sums [64][8]

// ---------------------------------------------------------------------------
// Packed f32x2 helpers (sm_103a; PTX-only path, ptxas never emits from C++)
// ---------------------------------------------------------------------------
__device__ __forceinline__ unsigned long long f2_pack(float lo, float hi) {
    unsigned long long d;
    asm("mov.b64 %0, {%1, %2};" : "=l"(d) : "f"(lo), "f"(hi));
    return d;
}
__device__ __forceinline__ void f2_unpack(unsigned long long v, float& lo, float& hi) {
    asm("mov.b64 {%0, %1}, %2;" : "=f"(lo), "=f"(hi) : "l"(v));
}
__device__ __forceinline__ unsigned long long f2_mul(unsigned long long a, unsigned long long b) {
    unsigned long long d;
    asm("mul.rn.f32x2 %0, %1, %2;" : "=l"(d) : "l"(a), "l"(b));
    return d;
}
__device__ __forceinline__ unsigned long long f2_add(unsigned long long a, unsigned long long b) {
    unsigned long long d;
    asm("add.rn.f32x2 %0, %1, %2;" : "=l"(d) : "l"(a), "l"(b));
    return d;
}
__device__ __forceinline__ unsigned long long f2_fma(unsigned long long a, unsigned long long b,
                                                     unsigned long long c) {
    unsigned long long d;
    asm("fma.rn.f32x2 %0, %1, %2, %3;" : "=l"(d) : "l"(a), "l"(b), "l"(c));
    return d;
}

struct RedConsts {
    unsigned long long inv2pi2, magic2, nmagic2, nhi2, nlo2;
};

// Packed Cody-Waite reduction -> r in [-pi, pi] (both lanes).
// Magic-round exact: |x/2pi| <= ~163 << 2^22.
__device__ __forceinline__ unsigned long long f2_reduce(
    unsigned long long w, unsigned long long a, const RedConsts& rc) {
    unsigned long long x2 = f2_mul(w, a);
    unsigned long long kb = f2_fma(x2, rc.inv2pi2, rc.magic2);  // round-to-nearest
    unsigned long long k2 = f2_add(kb, rc.nmagic2);
    unsigned long long r2 = f2_fma(k2, rc.nhi2, x2);
    return f2_fma(k2, rc.nlo2, r2);
}

// MUFU path: reduce + 2x MUFU.COS + packed accumulate (6 FMA-ops, 2 MUFU / 2 cos)
__device__ __forceinline__ unsigned long long f2_cos_acc(
    unsigned long long w, unsigned long long a, const RedConsts& rc,
    unsigned long long acc) {
    unsigned long long r2 = f2_reduce(w, a, rc);
    float rl, rh;
    f2_unpack(r2, rl, rh);
    return f2_add(acc, f2_pack(__cosf(rl), __cosf(rh)));
}

struct PolyConsts {
    unsigned long long c1, c2, c3, c4, c5, c6, c7;
};

// Poly path: reduce + even deg-14 Taylor, all on FMA pipe (13 ops / 2 cos).
// Computes acc += (cos(x) - 1) packed; caller adds the +1 per value afterwards.
__device__ __forceinline__ unsigned long long f2_cos_poly_accm1(
    unsigned long long w, unsigned long long a, const RedConsts& rc,
    const PolyConsts& pc, unsigned long long acc) {
    unsigned long long r2 = f2_reduce(w, a, rc);
    unsigned long long u  = f2_mul(r2, r2);
    unsigned long long t  = f2_fma(pc.c7, u, pc.c6);
    t = f2_fma(t, u, pc.c5);
    t = f2_fma(t, u, pc.c4);
    t = f2_fma(t, u, pc.c3);
    t = f2_fma(t, u, pc.c2);
    t = f2_fma(t, u, pc.c1);
    return f2_fma(t, u, acc);     // acc += u * t = cos(x) - 1
}

// ---------------------------------------------------------------------------
// Kernel 1: feats[o,p,i] = mean_j cos(wm[o,p] * adj[o,i,j])
// Pipe balance: q = 1/8 of cos via packed Taylor poly (FMA pipe) instead of
// MUFU -> per-16-cos cost FMA 110 / MUFU 112 cyc (was 96/128, MUFU-bound).
// Model: 8 -> 7 cyc/cos, ~12.5% faster feats.
// ---------------------------------------------------------------------------
__global__ __launch_bounds__(256, 2) void k_feats(const float* __restrict__ adj,
                                                  const float* __restrict__ wm) {
    const int bo = blockIdx.x;        // 0..6143
    const int o  = bo >> 11;
    const int i  = bo & (NN - 1);
    const int tid  = threadIdx.x;
    const int lane = tid & 31;
    const int wrp  = tid >> 5;

    const float INV2PI   = 0.15915494309189535f;
    const float TWOPI_HI = 6.28125f;               // exact in fp32
    const float TWOPI_LO = 1.9353071795864769e-3f; // 2pi - hi
    const float MAGIC    = 12582912.0f;            // 1.5 * 2^23
    RedConsts rc;
    rc.inv2pi2 = f2_pack(INV2PI, INV2PI);
    rc.magic2  = f2_pack(MAGIC, MAGIC);
    rc.nmagic2 = f2_pack(-MAGIC, -MAGIC);
    rc.nhi2    = f2_pack(-TWOPI_HI, -TWOPI_HI);
    rc.nlo2    = f2_pack(-TWOPI_LO, -TWOPI_LO);

    // cos(x) = 1 + u*(c1 + u*(c2 + ... )) with u = x^2 (Taylor deg 14)
    PolyConsts pc;
    pc.c1 = f2_pack(-0.5f, -0.5f);
    pc.c2 = f2_pack(4.1666666666666664e-02f, 4.1666666666666664e-02f);
    pc.c3 = f2_pack(-1.3888888888888889e-03f, -1.3888888888888889e-03f);
    pc.c4 = f2_pack(2.4801587301587302e-05f, 2.4801587301587302e-05f);
    pc.c5 = f2_pack(-2.7557319223985893e-07f, -2.7557319223985893e-07f);
    pc.c6 = f2_pack(2.0876756987868099e-09f, 2.0876756987868099e-09f);
    pc.c7 = f2_pack(-1.1470745597729725e-11f, -1.1470745597729725e-11f);

    unsigned long long w2[POINTS];
#pragma unroll
    for (int p = 0; p < POINTS; p++) {
        float w = wm[o * POINTS + p];
        w2[p] = f2_pack(w, w);
    }

    const float4* row4 =
        (const float4*)(adj + (size_t)o * NN * NN + (size_t)i * NN);

    float4 a0 = row4[tid];
    float4 a1 = row4[256 + tid];
    unsigned long long d0 = f2_pack(a0.x, a0.y);
    unsigned long long d1 = f2_pack(a0.z, a0.w);
    unsigned long long d2 = f2_pack(a1.x, a1.y);
    unsigned long long d3 = f2_pack(a1.z, a1.w);

    unsigned long long acc2[POINTS];
    const unsigned long long zero2 = f2_pack(0.0f, 0.0f);
#pragma unroll
    for (int p = 0; p < POINTS; p++) acc2[p] = zero2;

#pragma unroll
    for (int p = 0; p < POINTS; p++) {
        unsigned long long a = acc2[p];
        a = f2_cos_acc(w2[p], d0, rc, a);
        a = f2_cos_acc(w2[p], d1, rc, a);
        a = f2_cos_acc(w2[p], d2, rc, a);
        if (p & 1) {
            // poly path for pair d3 on odd p  (q = 1/8 of all cos)
            a = f2_cos_poly_accm1(w2[p], d3, rc, pc, a);
        } else {
            a = f2_cos_acc(w2[p], d3, rc, a);
        }
        acc2[p] = a;
    }

    // collapse packed lanes (+2.0 poly "+1"-correction on odd p), warp reduce
    float acc[POINTS];
#pragma unroll
    for (int p = 0; p < POINTS; p++) {
        float lo, hi;
        f2_unpack(acc2[p], lo, hi);
        acc[p] = lo + hi + ((p & 1) ? 2.0f : 0.0f);
    }
#pragma unroll
    for (int p = 0; p < POINTS; p++) {
#pragma unroll
        for (int off = 16; off > 0; off >>= 1)
            acc[p] += __shfl_xor_sync(0xFFFFFFFFu, acc[p], off);
    }

    __shared__ float red[8][POINTS];
    if (lane == 0) {
#pragma unroll
        for (int p = 0; p < POINTS; p++) red[wrp][p] = acc[p];
    }
    __syncthreads();

    if (tid < POINTS) {
        float s = 0.0f;
#pragma unroll
        for (int w = 0; w < 8; w++) s += red[w][tid];
        g_ms[i * OP + o * POINTS + tid] = s * (1.0f / (float)NN);
    }
}

// ---------------------------------------------------------------------------
// Kernel 2 (fused MLP): 4 rows per 256-thread block
// ---------------------------------------------------------------------------
__global__ __launch_bounds__(256) void k_mlp(const float* __restrict__ w1,
                                             const float* __restrict__ b1,
                                             const float* __restrict__ w2,
                                             const float* __restrict__ b2,
                                             const float* __restrict__ p1,
                                             const float* __restrict__ pb1,
                                             const float* __restrict__ p2,
                                             const float* __restrict__ pb2) {
    const int tid = threadIdx.x;
    const int r   = tid >> 6;
    const int t   = tid & 63;
    const int i   = blockIdx.x * 4 + r;

    __shared__ float sms[4][OP];
    __shared__ float sh1[4][D1];
    __shared__ float sh2[4][D2];
    __shared__ float sab[4][POOL1];

    if (t < OP) sms[r][t] = g_ms[i * OP + t];
    __syncthreads();

    {
        float s = b1[t];
#pragma unroll
        for (int k = 0; k < OP; k++) s = fmaf(sms[r][k], w1[k * D1 + t], s);
        sh1[r][t] = fmaxf(s, 0.0f);
    }
    __syncthreads();

    if (t < D2) {
        float s = b2[t];
#pragma unroll
        for (int k = 0; k < D1; k++) s = fmaf(sh1[r][k], w2[k * D2 + t], s);
        float h = fmaxf(s, 0.0f);
        sh2[r][t] = h;
        g_h2[i * D2 + t] = h;
    }
    __syncthreads();

    if (t < POOL1) {
        float a = pb1[t];
#pragma unroll
        for (int k = 0; k < D2; k++) a = fmaf(sh2[r][k], p1[k * POOL1 + t], a);
        sab[r][t] = tanhf(a);
    }
    __syncthreads();

    if (t < POOL2) {
        float s = pb2[t];
#pragma unroll
        for (int k = 0; k < POOL1; k++) s = fmaf(sab[r][k], p2[k * POOL2 + t], s);
        g_e[i * POOL2 + t] = expf(s);
    }
}

// ---------------------------------------------------------------------------
// Kernel 3: pooled partials + per-block e-sums. Deterministic (no atomics).
// ---------------------------------------------------------------------------
__global__ __launch_bounds__(256) void k_pool() {
    const int b    = blockIdx.x;
    const int tid  = threadIdx.x;
    const int lane = tid & 31;
    const int wrp  = tid >> 5;

    float acc[POOL2];
    float eacc[POOL2];
#pragma unroll
    for (int k = 0; k < POOL2; k++) { acc[k] = 0.0f; eacc[k] = 0.0f; }

    const int i0 = b * PROWS + wrp * 4;
#pragma unroll
    for (int t = 0; t < 4; t++) {
        int i = i0 + t;
        float h2v = g_h2[i * D2 + lane];
        float ev  = (lane < POOL2) ? g_e[i * POOL2 + lane] : 0.0f;
#pragma unroll
        for (int k = 0; k < POOL2; k++) {
            float ek = __shfl_sync(0xFFFFFFFFu, ev, k);
            acc[k]  = fmaf(ek, h2v, acc[k]);
            eacc[k] += ek;
        }
    }

    __shared__ float part[8][POOL2 * D2];
    __shared__ float parte[8][POOL2];
#pragma unroll
    for (int k = 0; k < POOL2; k++) part[wrp][k * D2 + lane] = acc[k];
    if (lane == 0) {
#pragma unroll
        for (int k = 0; k < POOL2; k++) parte[wrp][k] = eacc[k];
    }
    __syncthreads();

    float s = 0.0f;
#pragma unroll
    for (int w = 0; w < 8; w++) s += part[w][tid];
    g_part[b * (POOL2 * D2) + tid] = s;

    if (tid < POOL2) {
        float es = 0.0f;
#pragma unroll
        for (int w = 0; w < 8; w++) es += parte[w][tid];
        g_esum[b * POOL2 + tid] = es;
    }
}

// ---------------------------------------------------------------------------
// Kernel 4 (single block, 1024 threads): was 15.8us measured (serial L2
// chains, occ 12%, issue 3%). Now: 4-way split + unrolled independent loads
// (MLP>=16), esums from tiny g_esum, warp-per-label logits. Predicted ~2-3us.
// ---------------------------------------------------------------------------
__global__ __launch_bounds__(1024) void k_final(const float* __restrict__ cw,
                                                const float* __restrict__ cb,
                                                float* __restrict__ out) {
    const int tid  = threadIdx.x;
    const int lane = tid & 31;
    const int wrp  = tid >> 5;

    __shared__ float s_es[PBLK][POOL2];
    __shared__ float ssum[POOL2];
    __shared__ float sgp[4][POOL2 * D2];
    __shared__ float sg[POOL2 * D2];
    __shared__ float slog[LABELS];
    __shared__ float snorm[2];

    if (tid < PBLK * POOL2) {
        s_es[tid >> 3][tid & 7] = g_esum[tid];
    }

    {
        int q = tid >> 8;          // 0..3
        int j = tid & 255;
        float s = 0.0f;
#pragma unroll
        for (int b = 0; b < 16; b++)
            s += g_part[(q * 16 + b) * (POOL2 * D2) + j];
        sgp[q][j] = s;
    }
    __syncthreads();

    if (tid < POOL2) {
        float s = 0.0f;
#pragma unroll
        for (int b = 0; b < PBLK; b++) s += s_es[b][tid];
        ssum[tid] = s;
    }
    __syncthreads();

    if (tid < POOL2 * D2) {
        float s = (sgp[0][tid] + sgp[1][tid]) + (sgp[2][tid] + sgp[3][tid]);
        sg[tid] = s / ssum[tid >> 5];
    }
    __syncthreads();

    if (wrp < LABELS) {
        float s = 0.0f;
#pragma unroll
        for (int t = 0; t < 8; t++) {
            int j = t * 32 + lane;
            s = fmaf(sg[j], cw[j * LABELS + wrp], s);
        }
#pragma unroll
        for (int off = 16; off > 0; off >>= 1)
            s += __shfl_xor_sync(0xFFFFFFFFu, s, off);
        if (lane == 0) slog[wrp] = s + cb[wrp];
    }
    __syncthreads();

    if (tid == 0) {
        float m = -1e30f;
#pragma unroll
        for (int l = 0; l < LABELS; l++) m = fmaxf(m, slog[l]);
        float s = 0.0f;
#pragma unroll
        for (int l = 0; l < LABELS; l++) s += expf(slog[l] - m);
        snorm[0] = m;
        snorm[1] = logf(s);
    }
    __syncthreads();
    if (tid < LABELS) {
        out[tid] = slog[tid] - snorm[0] - snorm[1];
    }
}

// ---------------------------------------------------------------------------
extern "C" void kernel_launch(void* const* d_in, const int* in_sizes, int n_in,
                              void* d_out, int out_size) {
    const float* adj = (const float*)d_in[0];
    const float* wm  = (const float*)d_in[1];
    const float* w1  = (const float*)d_in[2];
    const float* b1  = (const float*)d_in[3];
    const float* w2  = (const float*)d_in[4];
    const float* b2  = (const float*)d_in[5];
    const float* p1  = (const float*)d_in[6];
    const float* pb1 = (const float*)d_in[7];
    const float* p2  = (const float*)d_in[8];
    const float* pb2 = (const float*)d_in[9];
    const float* cw  = (const float*)d_in[10];
    const float* cb  = (const float*)d_in[11];
    float* out = (float*)d_out;

    k_feats<<<ORDER * NN, 256>>>(adj, wm);
    k_mlp<<<NN / 4, 256>>>(w1, b1, w2, b2, p1, pb1, p2, pb2);
    k_pool<<<PBLK, 256>>>();
    k_final<<<1, 1024>>>(cw, cb, out);
}